// round 12
// baseline (speedup 1.0000x reference)
#include <cuda_runtime.h>
#include <cstdint>

#define B_    32
#define IC_   16
#define OC_   16
#define KTOT  65536      // (M-1)*(N-1)
#define E_    131584     // edges
#define VOFF  65792      // M*(N-1)
#define KT    32         // k per tile (never crosses a 256-wide row)

__device__ __forceinline__ unsigned long long pack2(float lo, float hi) {
    unsigned long long r;
    asm("mov.b64 %0, {%1, %2};" : "=l"(r) : "f"(lo), "f"(hi));
    return r;
}
__device__ __forceinline__ void fma2(unsigned long long &acc,
                                     unsigned long long a, unsigned long long b) {
    asm("fma.rn.f32x2 %0, %1, %2, %0;" : "+l"(acc) : "l"(a), "l"(b));
}
__device__ __forceinline__ float2 unpack2(unsigned long long v) {
    float2 f;
    asm("mov.b64 {%0, %1}, %2;" : "=f"(f.x), "=f"(f.y) : "l"(v));
    return f;
}
__device__ __forceinline__ ulonglong2 ldg128(const void* p) {
    ulonglong2 v;
    asm("ld.global.nc.v2.u64 {%0, %1}, [%2];"
        : "=l"(v.x), "=l"(v.y) : "l"(p));
    return v;
}

// ZERO-SYNC kernel: no smem, no barriers, no cp.async.
// Block: 32 k-lanes x 16 warps (y = oh*8 + bg). Warp reads its 8 weight rows
// (o = oh*8 .. oh*8+7) directly via LDG.128: the 8 bg-warps of an oh-half read
// IDENTICAL 512B lines -> 7/8 L1 hits; first touch MSHR-merges so DRAM traffic
// stays 1x. x rows are shared by the 2 oh-halves the same way. All 16 warps
// free-run; stragglers cannot propagate.
__global__ __launch_bounds__(512, 1)
void edges_kernel(const float* __restrict__ x,
                  const float4* __restrict__ w4,
                  const float* __restrict__ bias,
                  float* __restrict__ out)
{
    const int lane = threadIdx.x;
    const int y    = threadIdx.y;
    const int oh   = y >> 3;
    const int bg   = y & 7;
    const int bbase = bg * 4;

    const int k0 = blockIdx.x * KT;
    const int k  = k0 + lane;
    const int i  = k0 >> 8;
    const int c0 = k;                                   // t0; t1 = c0+256
    const int c2 = VOFF + i * 257 + (k0 & 255) + lane;  // t2; t3 = c2+1

    // weight row pointer for this thread: o = oh*8 + oo, element (ic, k)
    // index = ((oh*8+oo)*IC + ic)*KTOT + k ; advance by KTOT per ic
    const float4* wrow0 = w4 + (size_t)((oh * 8) * IC_) * KTOT + k;
    const size_t  wostr = (size_t)IC_ * KTOT;           // per-o stride (float4s)

    const float* xp[4];
    #pragma unroll
    for (int bb = 0; bb < 4; ++bb)
        xp[bb] = x + (size_t)((bbase + bb) * IC_) * E_;

    unsigned long long acc[8][4];
    #pragma unroll
    for (int oo = 0; oo < 8; ++oo)
        #pragma unroll
        for (int bb = 0; bb < 4; ++bb) acc[oo][bb] = 0ull;

    // prologue: x gather for ic = 0
    float xf[4][4];
    #pragma unroll
    for (int bb = 0; bb < 4; ++bb) {
        const float* xb = xp[bb];
        xf[bb][0] = __ldg(xb + c0);
        xf[bb][1] = __ldg(xb + c0 + 256);
        xf[bb][2] = __ldg(xb + c2);
        xf[bb][3] = __ldg(xb + c2 + 1);
    }

    #pragma unroll 1
    for (int ic = 0; ic < IC_; ++ic) {
        // pack current x, then prefetch next ic's x (overwrites xf)
        unsigned long long xA[4], xB[4];
        #pragma unroll
        for (int bb = 0; bb < 4; ++bb) {
            xA[bb] = pack2(xf[bb][0], xf[bb][1]);
            xB[bb] = pack2(xf[bb][2], xf[bb][3]);
        }
        if (ic < IC_ - 1) {
            const int off = (ic + 1) * E_;
            #pragma unroll
            for (int bb = 0; bb < 4; ++bb) {
                const float* xb = xp[bb] + off;
                xf[bb][0] = __ldg(xb + c0);
                xf[bb][1] = __ldg(xb + c0 + 256);
                xf[bb][2] = __ldg(xb + c2);
                xf[bb][3] = __ldg(xb + c2 + 1);
            }
        }

        const float4* wic = wrow0 + (size_t)ic * KTOT;

        // two halves of 4 o each: keeps w live-range at 16 regs
        #pragma unroll
        for (int hf = 0; hf < 2; ++hf) {
            ulonglong2 wv[4];
            #pragma unroll
            for (int q = 0; q < 4; ++q)
                wv[q] = ldg128(wic + (size_t)(hf * 4 + q) * wostr);
            #pragma unroll
            for (int q = 0; q < 4; ++q) {
                const int oo = hf * 4 + q;
                #pragma unroll
                for (int bb = 0; bb < 4; ++bb) {
                    fma2(acc[oo][bb], wv[q].x, xA[bb]);
                    fma2(acc[oo][bb], wv[q].y, xB[bb]);
                }
            }
        }
    }

    // epilogue: lo+hi + bias, coalesced STG.32
    #pragma unroll
    for (int oo = 0; oo < 8; ++oo) {
        const int o = oh * 8 + oo;
        const float bo = __ldg(&bias[o]);
        #pragma unroll
        for (int bb = 0; bb < 4; ++bb) {
            float2 v = unpack2(acc[oo][bb]);
            out[(size_t)((bbase + bb) * OC_ + o) * KTOT + k] = v.x + v.y + bo;
        }
    }
}

extern "C" void kernel_launch(void* const* d_in, const int* in_sizes, int n_in,
                              void* d_out, int out_size)
{
    const float*  x    = (const float*)d_in[0];
    const float4* w4   = (const float4*)d_in[1];
    const float*  bias = (const float*)d_in[2];
    float*        out  = (float*)d_out;

    dim3 block(32, 16);
    dim3 grid(KTOT / KT);   // 2048
    edges_kernel<<<grid, block>>>(x, w4, bias, out);
}

// round 13
// speedup vs baseline: 1.8193x; 1.8193x over previous
#include <cuda_runtime.h>
#include <cstdint>

#define B_    32
#define IC_   16
#define OC_   16
#define KTOT  65536      // (M-1)*(N-1)
#define E_    131584     // edges
#define VOFF  65792      // M*(N-1)
#define KT    32         // k per tile (never crosses a 256-wide row)
#define NBUF  4          // weight pipeline depth

__device__ __forceinline__ void cp_async16(unsigned dst, const void* src) {
    asm volatile("cp.async.cg.shared.global [%0], [%1], 16;\n"
                 :: "r"(dst), "l"(src) : "memory");
}
__device__ __forceinline__ void cp_commit() {
    asm volatile("cp.async.commit_group;\n" ::: "memory");
}
template<int N>
__device__ __forceinline__ void cp_wait() {
    asm volatile("cp.async.wait_group %0;\n" :: "n"(N) : "memory");
}

// CTA: 32 k-lanes x 8 warps (bg), 256 threads, 3 CTAs/SM (24 warps).
// CTA owns one oh-half (8 o-channels) x all 32 batches x one 32-wide k-tile.
// o-ranges are disjoint across the 2 CTAs of a tile => weights stream from
// DRAM exactly once. Scalar FFMA accumulation keeps acc at 32 regs so three
// 256-thread CTAs (three independent pipeline domains) fit per SM.
__global__ __launch_bounds__(256, 3)
void edges_kernel(const float* __restrict__ x,
                  const float4* __restrict__ w4,
                  const float* __restrict__ bias,
                  float* __restrict__ out)
{
    __shared__ float4 sw[NBUF][8 * KT];   // [buf][olocal*32 + klocal], 4 KB/buf

    const int lane = threadIdx.x;
    const int bg   = threadIdx.y;          // 0..7
    const int bbase = bg * 4;

    const int oh   = blockIdx.x & 1;
    const int tile = blockIdx.x >> 1;

    const int k0 = tile * KT;
    const int k  = k0 + lane;
    const int i  = k0 >> 8;
    const int c0 = k;                                   // t0; t1 = c0+256
    const int c2 = VOFF + i * 257 + (k0 & 255) + lane;  // t2; t3 = c2+1

    // cooperative weight copy: 256 threads x 16B = one 4 KB slab per ic
    const int tld = bg * 32 + lane;
    const float4* wsrc = w4
        + (size_t)((oh * 8 + (tld >> 5)) * IC_) * KTOT + k0 + (tld & 31);
    const unsigned swdst0 = (unsigned)__cvta_generic_to_shared(&sw[0][tld]);

    const float* xp[4];
    #pragma unroll
    for (int bb = 0; bb < 4; ++bb)
        xp[bb] = x + (size_t)((bbase + bb) * IC_) * E_;

    float acc[8][4];
    #pragma unroll
    for (int oo = 0; oo < 8; ++oo)
        #pragma unroll
        for (int bb = 0; bb < 4; ++bb) acc[oo][bb] = 0.f;

    // prologue: weight stages 0..2
    #pragma unroll
    for (int s = 0; s < 3; ++s) {
        cp_async16(swdst0 + s * (8 * KT * 16), wsrc + (size_t)s * KTOT);
        cp_commit();
    }

    #pragma unroll 1
    for (int ic = 0; ic < IC_; ++ic) {
        if (ic <= IC_ - 3)      cp_wait<2>();
        else if (ic == IC_ - 2) cp_wait<1>();
        else                    cp_wait<0>();
        __syncthreads();

        if (ic + 3 < IC_) {
            cp_async16(swdst0 + ((ic + 3) & (NBUF - 1)) * (8 * KT * 16),
                       wsrc + (size_t)(ic + 3) * KTOT);
            cp_commit();
        }

        // x gather for this ic (latency hidden by 24-warp occupancy)
        float xf[4][4];
        const int off = ic * E_;
        #pragma unroll
        for (int bb = 0; bb < 4; ++bb) {
            const float* xb = xp[bb] + off;
            xf[bb][0] = __ldg(xb + c0);
            xf[bb][1] = __ldg(xb + c0 + 256);
            xf[bb][2] = __ldg(xb + c2);
            xf[bb][3] = __ldg(xb + c2 + 1);
        }

        // compute: 8 o x 4 b x 4 t scalar FFMA
        const unsigned sa = (unsigned)__cvta_generic_to_shared(
                                &sw[ic & (NBUF - 1)][lane]);
        #pragma unroll
        for (int oo = 0; oo < 8; ++oo) {
            float4 w;
            asm("ld.shared.v4.f32 {%0, %1, %2, %3}, [%4];"
                : "=f"(w.x), "=f"(w.y), "=f"(w.z), "=f"(w.w)
                : "r"(sa + oo * (KT * 16)));
            #pragma unroll
            for (int bb = 0; bb < 4; ++bb) {
                acc[oo][bb] += w.x * xf[bb][0];
                acc[oo][bb] += w.y * xf[bb][1];
                acc[oo][bb] += w.z * xf[bb][2];
                acc[oo][bb] += w.w * xf[bb][3];
            }
        }
    }

    // epilogue: + bias, coalesced STG.32
    #pragma unroll
    for (int oo = 0; oo < 8; ++oo) {
        const int o = oh * 8 + oo;
        const float bo = __ldg(&bias[o]);
        #pragma unroll
        for (int bb = 0; bb < 4; ++bb)
            out[(size_t)((bbase + bb) * OC_ + o) * KTOT + k] = acc[oo][bb] + bo;
    }
}

extern "C" void kernel_launch(void* const* d_in, const int* in_sizes, int n_in,
                              void* d_out, int out_size)
{
    const float*  x    = (const float*)d_in[0];
    const float4* w4   = (const float4*)d_in[1];
    const float*  bias = (const float*)d_in[2];
    float*        out  = (float*)d_out;

    dim3 block(32, 8);
    dim3 grid((KTOT / KT) * 2);   // 4096 CTAs: (tile, oh-half)
    edges_kernel<<<grid, block>>>(x, w4, bias, out);
}

// round 14
// speedup vs baseline: 1.9617x; 1.0783x over previous
#include <cuda_runtime.h>
#include <cstdint>

#define B_    32
#define IC_   16
#define OC_   16
#define KTOT  65536      // (M-1)*(N-1)
#define E_    131584     // edges
#define VOFF  65792      // M*(N-1)
#define KT    32         // k per tile (never crosses a 256-wide row)
#define NBUF  4          // weight pipeline depth
#define BSTR  ((size_t)IC_ * E_)   // x stride per batch (floats)

__device__ __forceinline__ void cp_async16(unsigned dst, const void* src) {
    asm volatile("cp.async.cg.shared.global [%0], [%1], 16;\n"
                 :: "r"(dst), "l"(src) : "memory");
}
__device__ __forceinline__ void cp_commit() {
    asm volatile("cp.async.commit_group;\n" ::: "memory");
}
template<int N>
__device__ __forceinline__ void cp_wait() {
    asm volatile("cp.async.wait_group %0;\n" :: "n"(N) : "memory");
}

// CTA: 32 k-lanes x 8 warps (bg), 256 threads, 4 CTAs/SM (32 warps).
// CTA owns one oh-half (8 o) x all 32 batches x one 32-wide k-tile.
// o-ranges disjoint across the 2 CTAs of a tile => weights stream from DRAM
// exactly once. Scalar FFMA keeps acc at 32 regs; 64-reg budget -> occ 4.
__global__ __launch_bounds__(256, 4)
void edges_kernel(const float* __restrict__ x,
                  const float4* __restrict__ w4,
                  const float* __restrict__ bias,
                  float* __restrict__ out)
{
    __shared__ float4 sw[NBUF][8 * KT];   // [buf][olocal*32 + klocal], 4 KB/buf

    const int lane = threadIdx.x;
    const int bg   = threadIdx.y;          // 0..7
    const int bbase = bg * 4;

    const int oh   = blockIdx.x & 1;
    const int tile = blockIdx.x >> 1;

    const int k0 = tile * KT;
    const int k  = k0 + lane;
    const int i  = k0 >> 8;
    const int c0 = k;                                   // t0; t1 = c0+256
    const int c2 = VOFF + i * 257 + (k0 & 255) + lane;  // t2; t3 = c2+1

    // cooperative weight copy: 256 threads x 16B = one 4 KB slab per ic
    const int tld = bg * 32 + lane;
    const float4* wsrc = w4
        + (size_t)((oh * 8 + (tld >> 5)) * IC_) * KTOT + k0 + (tld & 31);
    const unsigned swdst0 = (unsigned)__cvta_generic_to_shared(&sw[0][tld]);

    // single x base for this thread's batch group (per-ic, per-bb derived)
    const float* xbase = x + (size_t)bbase * BSTR;

    // bias folded into accumulator init: acc[oo][*] starts at bias[o]
    float acc[8][4];
    #pragma unroll
    for (int oo = 0; oo < 8; ++oo) {
        const float bo = __ldg(&bias[oh * 8 + oo]);
        #pragma unroll
        for (int bb = 0; bb < 4; ++bb) acc[oo][bb] = bo;
    }

    // prologue: weight stages 0..2
    #pragma unroll
    for (int s = 0; s < 3; ++s) {
        cp_async16(swdst0 + s * (8 * KT * 16), wsrc + (size_t)s * KTOT);
        cp_commit();
    }

    #pragma unroll 1
    for (int ic = 0; ic < IC_; ++ic) {
        if (ic <= IC_ - 3)      cp_wait<2>();
        else if (ic == IC_ - 2) cp_wait<1>();
        else                    cp_wait<0>();
        __syncthreads();

        if (ic + 3 < IC_) {
            cp_async16(swdst0 + ((ic + 3) & (NBUF - 1)) * (8 * KT * 16),
                       wsrc + (size_t)(ic + 3) * KTOT);
            cp_commit();
        }

        // x gather for this ic (latency hidden by 32-warp occupancy)
        float xf[4][4];
        const float* p = xbase + (size_t)ic * E_;
        #pragma unroll
        for (int bb = 0; bb < 4; ++bb) {
            const float* xb = p + (size_t)bb * BSTR;
            xf[bb][0] = __ldg(xb + c0);
            xf[bb][1] = __ldg(xb + c0 + 256);
            xf[bb][2] = __ldg(xb + c2);
            xf[bb][3] = __ldg(xb + c2 + 1);
        }

        // compute: 8 o x 4 b x 4 t scalar FFMA
        const unsigned sa = (unsigned)__cvta_generic_to_shared(
                                &sw[ic & (NBUF - 1)][lane]);
        #pragma unroll
        for (int oo = 0; oo < 8; ++oo) {
            float4 w;
            asm("ld.shared.v4.f32 {%0, %1, %2, %3}, [%4];"
                : "=f"(w.x), "=f"(w.y), "=f"(w.z), "=f"(w.w)
                : "r"(sa + oo * (KT * 16)));
            #pragma unroll
            for (int bb = 0; bb < 4; ++bb) {
                acc[oo][bb] += w.x * xf[bb][0];
                acc[oo][bb] += w.y * xf[bb][1];
                acc[oo][bb] += w.z * xf[bb][2];
                acc[oo][bb] += w.w * xf[bb][3];
            }
        }
    }

    // epilogue: coalesced STG.32 (bias already included)
    #pragma unroll
    for (int oo = 0; oo < 8; ++oo) {
        const int o = oh * 8 + oo;
        #pragma unroll
        for (int bb = 0; bb < 4; ++bb)
            out[(size_t)((bbase + bb) * OC_ + o) * KTOT + k] = acc[oo][bb];
    }
}

extern "C" void kernel_launch(void* const* d_in, const int* in_sizes, int n_in,
                              void* d_out, int out_size)
{
    const float*  x    = (const float*)d_in[0];
    const float4* w4   = (const float4*)d_in[1];
    const float*  bias = (const float*)d_in[2];
    float*        out  = (float*)d_out;

    dim3 block(32, 8);
    dim3 grid((KTOT / KT) * 2);   // 4096 CTAs: (tile, oh-half)
    edges_kernel<<<grid, block>>>(x, w4, bias, out);
}

// round 15
// speedup vs baseline: 2.2147x; 1.1289x over previous
#include <cuda_runtime.h>
#include <cstdint>

#define B_    32
#define IC_   16
#define OC_   16
#define KTOT  65536      // (M-1)*(N-1)
#define E_    131584     // edges
#define VOFF  65792      // M*(N-1)
#define KT    32         // k per tile (never crosses a 256-wide row)
#define NBUF  6          // weight pipeline depth (6 x 4KB = 24KB smem/CTA)
#define LOOKA 5          // issue lookahead (stage ic+5)
#define BSTR  ((size_t)IC_ * E_)   // x stride per batch (floats)

__device__ __forceinline__ void cp_async16(unsigned dst, const void* src) {
    asm volatile("cp.async.cg.shared.global [%0], [%1], 16;\n"
                 :: "r"(dst), "l"(src) : "memory");
}
__device__ __forceinline__ void cp_commit() {
    asm volatile("cp.async.commit_group;\n" ::: "memory");
}
template<int N>
__device__ __forceinline__ void cp_wait() {
    asm volatile("cp.async.wait_group %0;\n" :: "n"(N) : "memory");
}

// CTA: 32 k-lanes x 8 warps (bg), 256 threads, 4 CTAs/SM (32 warps).
// CTA owns one oh-half (8 o) x all 32 batches x one 32-wide k-tile.
// o-ranges disjoint across the 2 CTAs of a tile => weights stream from DRAM
// exactly once. x gather hoisted ABOVE the barrier so its latency overlaps
// the cp-wait/barrier window. 6-deep weight pipeline (~4 iters of slack).
__global__ __launch_bounds__(256, 4)
void edges_kernel(const float* __restrict__ x,
                  const float4* __restrict__ w4,
                  const float* __restrict__ bias,
                  float* __restrict__ out)
{
    __shared__ float4 sw[NBUF][8 * KT];   // [buf][olocal*32 + klocal], 4 KB/buf

    const int lane = threadIdx.x;
    const int bg   = threadIdx.y;          // 0..7
    const int bbase = bg * 4;

    const int oh   = blockIdx.x & 1;
    const int tile = blockIdx.x >> 1;

    const int k0 = tile * KT;
    const int k  = k0 + lane;
    const int i  = k0 >> 8;
    const int c0 = k;                                   // t0; t1 = c0+256
    const int c2 = VOFF + i * 257 + (k0 & 255) + lane;  // t2; t3 = c2+1

    // cooperative weight copy: 256 threads x 16B = one 4 KB slab per ic
    const int tld = bg * 32 + lane;
    const float4* wsrc = w4
        + (size_t)((oh * 8 + (tld >> 5)) * IC_) * KTOT + k0 + (tld & 31);
    const unsigned swdst0 = (unsigned)__cvta_generic_to_shared(&sw[0][tld]);

    const float* xbase = x + (size_t)bbase * BSTR;

    // bias folded into accumulator init
    float acc[8][4];
    #pragma unroll
    for (int oo = 0; oo < 8; ++oo) {
        const float bo = __ldg(&bias[oh * 8 + oo]);
        #pragma unroll
        for (int bb = 0; bb < 4; ++bb) acc[oo][bb] = bo;
    }

    // prologue: weight stages 0..LOOKA-1
    #pragma unroll
    for (int s = 0; s < LOOKA; ++s) {
        cp_async16(swdst0 + (s % NBUF) * (8 * KT * 16), wsrc + (size_t)s * KTOT);
        cp_commit();
    }

    int buf = 0;
    #pragma unroll 1
    for (int ic = 0; ic < IC_; ++ic) {
        // x gather for this ic FIRST: overlaps the cp-wait + barrier below
        float xf[4][4];
        {
            const float* p = xbase + (size_t)ic * E_;
            #pragma unroll
            for (int bb = 0; bb < 4; ++bb) {
                const float* xb = p + (size_t)bb * BSTR;
                xf[bb][0] = __ldg(xb + c0);
                xf[bb][1] = __ldg(xb + c0 + 256);
                xf[bb][2] = __ldg(xb + c2);
                xf[bb][3] = __ldg(xb + c2 + 1);
            }
        }

        // wait for weight stage ic (keep younger stages in flight)
        {
            const int pend = ((IC_ - 1 - ic) < LOOKA ? (IC_ - 1 - ic) : LOOKA) - 1;
            if (pend >= 4)      cp_wait<4>();
            else if (pend == 3) cp_wait<3>();
            else if (pend == 2) cp_wait<2>();
            else if (pend == 1) cp_wait<1>();
            else                cp_wait<0>();
        }
        __syncthreads();

        // issue stage ic+LOOKA (reuses buffer freed by stage ic-1)
        if (ic + LOOKA < IC_) {
            const int nb = (ic + LOOKA) % NBUF;
            cp_async16(swdst0 + nb * (8 * KT * 16),
                       wsrc + (size_t)(ic + LOOKA) * KTOT);
            cp_commit();
        }

        // compute: 8 o x 4 b x 4 t scalar FFMA
        const unsigned sa = (unsigned)__cvta_generic_to_shared(&sw[buf][lane]);
        #pragma unroll
        for (int oo = 0; oo < 8; ++oo) {
            float4 w;
            asm("ld.shared.v4.f32 {%0, %1, %2, %3}, [%4];"
                : "=f"(w.x), "=f"(w.y), "=f"(w.z), "=f"(w.w)
                : "r"(sa + oo * (KT * 16)));
            #pragma unroll
            for (int bb = 0; bb < 4; ++bb) {
                acc[oo][bb] += w.x * xf[bb][0];
                acc[oo][bb] += w.y * xf[bb][1];
                acc[oo][bb] += w.z * xf[bb][2];
                acc[oo][bb] += w.w * xf[bb][3];
            }
        }

        if (++buf == NBUF) buf = 0;
    }

    // epilogue: coalesced STG.32 (bias already included)
    #pragma unroll
    for (int oo = 0; oo < 8; ++oo) {
        const int o = oh * 8 + oo;
        #pragma unroll
        for (int bb = 0; bb < 4; ++bb)
            out[(size_t)((bbase + bb) * OC_ + o) * KTOT + k] = acc[oo][bb];
    }
}

extern "C" void kernel_launch(void* const* d_in, const int* in_sizes, int n_in,
                              void* d_out, int out_size)
{
    const float*  x    = (const float*)d_in[0];
    const float4* w4   = (const float4*)d_in[1];
    const float*  bias = (const float*)d_in[2];
    float*        out  = (float*)d_out;

    dim3 block(32, 8);
    dim3 grid((KTOT / KT) * 2);   // 4096 CTAs: (tile, oh-half)
    edges_kernel<<<grid, block>>>(x, w4, bias, out);
}